// round 6
// baseline (speedup 1.0000x reference)
#include <cuda_runtime.h>
#include <cstdint>
#include <cstddef>

// Problem constants
#define B_ 64
#define T_ 1024
#define I_ 128
#define H_ 256

#define GRP 8              // batch groups
#define BG 8               // batches per group
#define CLU 8              // CTAs per cluster (one cluster = one (layer,group) recurrence)
#define NCTA 128           // 64 L1 + 64 L2
#define TPB 256

#define OUT_Y2 ((size_t)B_ * T_ * H_)

// -------- device scratch --------
__device__ __align__(16) float g_xpre[(size_t)B_ * T_ * 512];            // [b][t][512]
__device__ __align__(16) float g_y1t[(size_t)(T_ + 1) * GRP * 2048];     // [t][g][b][k] (8KB slabs)
__device__ unsigned g_cnt1[GRP][T_ + 1];

// -------- PTX helpers --------
typedef unsigned long long u64;
__device__ __forceinline__ uint32_t s2u(const void* p) {
    return (uint32_t)__cvta_generic_to_shared(p);
}
__device__ __forceinline__ void mbar_init(uint32_t a, uint32_t cnt) {
    asm volatile("mbarrier.init.shared.b64 [%0], %1;" :: "r"(a), "r"(cnt) : "memory");
}
__device__ __forceinline__ void mbar_expect(uint32_t a, uint32_t bytes) {
    asm volatile("mbarrier.arrive.expect_tx.shared.b64 _, [%0], %1;" :: "r"(a), "r"(bytes) : "memory");
}
__device__ __forceinline__ void bulk_g2s(uint32_t dst, const void* src, uint32_t bytes, uint32_t mbar) {
    asm volatile("cp.async.bulk.shared::cluster.global.mbarrier::complete_tx::bytes [%0], [%1], %2, [%3];"
                 :: "r"(dst), "l"(src), "r"(bytes), "r"(mbar) : "memory");
}
__device__ __forceinline__ void mbar_wait(uint32_t a, uint32_t parity) {
    asm volatile("{\n\t"
                 ".reg .pred P;\n\t"
                 "W%=:\n\t"
                 "mbarrier.try_wait.parity.acquire.cta.shared::cta.b64 P, [%0], %1, 0x989680;\n\t"
                 "@P bra D%=;\n\t"
                 "bra W%=;\n\t"
                 "D%=:\n\t"
                 "}" :: "r"(a), "r"(parity) : "memory");
}
__device__ __forceinline__ void fence_async() {
    asm volatile("fence.proxy.async.shared::cta;" ::: "memory");
}
__device__ __forceinline__ unsigned ld_acq(const unsigned* p) {
    unsigned v;
    asm volatile("ld.global.acquire.gpu.u32 %0, [%1];" : "=r"(v) : "l"(p) : "memory");
    return v;
}
__device__ __forceinline__ void red_add1(unsigned* p) {
    asm volatile("red.release.gpu.global.add.u32 [%0], %1;" :: "l"(p), "r"(1u) : "memory");
}
__device__ __forceinline__ u64 pack2(float x, float y) {
    u64 r; asm("mov.b64 %0, {%1, %2};" : "=l"(r) : "f"(x), "f"(y)); return r;
}
__device__ __forceinline__ void unpack2(u64 v, float& x, float& y) {
    asm("mov.b64 {%0, %1}, %2;" : "=f"(x), "=f"(y) : "l"(v));
}
__device__ __forceinline__ u64 fma2(u64 a, u64 b, u64 c) {
    u64 d; asm("fma.rn.f32x2 %0, %1, %2, %3;" : "=l"(d) : "l"(a), "l"(b), "l"(c)); return d;
}
__device__ __forceinline__ u64 add2(u64 a, u64 b) {
    u64 d; asm("add.rn.f32x2 %0, %1, %2;" : "=l"(d) : "l"(a), "l"(b)); return d;
}
__device__ __forceinline__ float sigm(float x) { return 1.f / (1.f + __expf(-x)); }
__device__ __forceinline__ float tanh_f(float x) { return 1.f - 2.f / (1.f + __expf(2.f * x)); }
__device__ __forceinline__ uint32_t mapa_u32(uint32_t a, int r) {
    uint32_t d; asm("mapa.shared::cluster.u32 %0, %1, %2;" : "=r"(d) : "r"(a), "r"(r)); return d;
}
__device__ __forceinline__ void st_cluster_f32(uint32_t addr, float v) {
    asm volatile("st.shared::cluster.f32 [%0], %1;" :: "r"(addr), "f"(v) : "memory");
}
#define CL_ARRIVE() asm volatile("barrier.cluster.arrive.aligned;" ::: "memory")
#define CL_WAIT()   asm volatile("barrier.cluster.wait.aligned;"   ::: "memory")

// ============================================================
// Phase 1: x-projection GEMM (unchanged)
// ============================================================
__global__ void __launch_bounds__(256) xproj_kernel(
    const float* __restrict__ x,
    const float* __restrict__ Wf1, const float* __restrict__ bf1,
    const float* __restrict__ Wc1, const float* __restrict__ bc1)
{
    __shared__ float As[64][68];
    __shared__ float Bs[64][68];
    const int bm = blockIdx.x;
    const int bn = blockIdx.y;
    const int tid = threadIdx.x;
    const int tx = tid & 15, ty = tid >> 4;

    const float* W; const float* bias; int jb;
    if (bn < 4) { W = Wf1; bias = bf1; jb = bn * 64; }
    else        { W = Wc1; bias = bc1; jb = (bn - 4) * 64; }

    float acc[4][4];
#pragma unroll
    for (int i = 0; i < 4; ++i)
#pragma unroll
        for (int j = 0; j < 4; ++j) acc[i][j] = 0.f;

    for (int k0 = 0; k0 < 128; k0 += 64) {
#pragma unroll
        for (int i = 0; i < 4; ++i) {
            int idx = tid + i * 256;
            int r = idx >> 4, kv = idx & 15;
            float4 v = *(const float4*)(x + (size_t)(bm * 64 + r) * 128 + k0 + kv * 4);
            *(float4*)&As[r][kv * 4] = v;
        }
#pragma unroll
        for (int i = 0; i < 4; ++i) {
            int idx = tid + i * 256;
            int kk = idx >> 4, cv = idx & 15;
            float4 v = *(const float4*)(W + (size_t)(k0 + kk) * 256 + jb + cv * 4);
            *(float4*)&Bs[kk][cv * 4] = v;
        }
        __syncthreads();
#pragma unroll 16
        for (int kk = 0; kk < 64; ++kk) {
            float a0 = As[ty * 4 + 0][kk];
            float a1 = As[ty * 4 + 1][kk];
            float a2 = As[ty * 4 + 2][kk];
            float a3 = As[ty * 4 + 3][kk];
            float4 bv = *(const float4*)&Bs[kk][tx * 4];
            acc[0][0] = fmaf(a0, bv.x, acc[0][0]);
            acc[0][1] = fmaf(a0, bv.y, acc[0][1]);
            acc[0][2] = fmaf(a0, bv.z, acc[0][2]);
            acc[0][3] = fmaf(a0, bv.w, acc[0][3]);
            acc[1][0] = fmaf(a1, bv.x, acc[1][0]);
            acc[1][1] = fmaf(a1, bv.y, acc[1][1]);
            acc[1][2] = fmaf(a1, bv.z, acc[1][2]);
            acc[1][3] = fmaf(a1, bv.w, acc[1][3]);
            acc[2][0] = fmaf(a2, bv.x, acc[2][0]);
            acc[2][1] = fmaf(a2, bv.y, acc[2][1]);
            acc[2][2] = fmaf(a2, bv.z, acc[2][2]);
            acc[2][3] = fmaf(a2, bv.w, acc[2][3]);
            acc[3][0] = fmaf(a3, bv.x, acc[3][0]);
            acc[3][1] = fmaf(a3, bv.y, acc[3][1]);
            acc[3][2] = fmaf(a3, bv.z, acc[3][2]);
            acc[3][3] = fmaf(a3, bv.w, acc[3][3]);
        }
        __syncthreads();
    }
#pragma unroll
    for (int i = 0; i < 4; ++i) {
        int r = bm * 64 + ty * 4 + i;
        float4 o;
        o.x = acc[i][0] + bias[jb + tx * 4 + 0];
        o.y = acc[i][1] + bias[jb + tx * 4 + 1];
        o.z = acc[i][2] + bias[jb + tx * 4 + 2];
        o.w = acc[i][3] + bias[jb + tx * 4 + 3];
        *(float4*)&g_xpre[(size_t)r * 512 + bn * 64 + tx * 4] = o;
    }
}

// ============================================================
__global__ void init_kernel()
{
    int i = blockIdx.x * blockDim.x + threadIdx.x;
    if (i < GRP * (T_ + 1)) ((unsigned*)g_cnt1)[i] = 0;
}

// ============================================================
// Phase 2: clustered persistent recurrence
//   SMEM layout (dynamic):
//     [    0, 16384): bufA[2][8][256]  -- L1: h1 dbl-buf | L2: y dbl-buf (TMA dst)
//     [16384, 32768): bufB[2][8][256]  -- L2: h2 dbl-buf (DSMEM dst); L1 unused
//     [32768, 65536): red  u64[2][8][8][32] partials [gate][kq][b][j]
//     [65536, 67584): xs[2][8][32]     -- L1 xpre staging [gate][b][j]
//     [67584, 67600): mbar[2]
// ============================================================
#define SM_A    0
#define SM_B    16384
#define SM_RED  32768
#define SM_XS   65536
#define SM_MBAR 67584
#define SMEM_BYTES 67712

extern __shared__ __align__(16) char smem[];

__global__ void __launch_bounds__(TPB, 1) __cluster_dims__(CLU, 1, 1)
recur_kernel(const float* __restrict__ Wf1, const float* __restrict__ Wc1,
             const float* __restrict__ Wf2, const float* __restrict__ bf2,
             const float* __restrict__ Wc2, const float* __restrict__ bc2,
             float* __restrict__ out)
{
    const int tid = threadIdx.x;
    const int warp = tid >> 5, lane = tid & 31;
    const int cid = blockIdx.x;
    const bool isL1 = cid < 64;
    const int g = (cid & 63) >> 3;          // group
    const int rank = cid & 7;               // cluster rank
    const int j0 = rank * 32;
    const int jg = j0 + lane;               // this thread's column (GEMM & reduce phases)

    float* bufA = (float*)(smem + SM_A);
    float* bufB = (float*)(smem + SM_B);
    u64*   red  = (u64*)(smem + SM_RED);
    float* xs   = (float*)(smem + SM_XS);
    const uint32_t mb0 = s2u(smem + SM_MBAR);
    const uint32_t mb1 = mb0 + 8;

    if (isL1) {
        // ================= Layer 1: one cluster per group, 32 cols/CTA =================
        u64 wf[16], wc[16];
#pragma unroll
        for (int p = 0; p < 16; ++p) {
            int k = warp * 32 + 2 * p;
            wf[p] = pack2(Wf1[(size_t)(I_ + k) * H_ + jg], Wf1[(size_t)(I_ + k + 1) * H_ + jg]);
            wc[p] = pack2(Wc1[(size_t)(I_ + k) * H_ + jg], Wc1[(size_t)(I_ + k + 1) * H_ + jg]);
        }
        uint32_t rem[8];
#pragma unroll
        for (int r = 0; r < 8; ++r) rem[r] = mapa_u32(s2u(bufA), r);

        for (int i = tid; i < 2048; i += TPB) bufA[i] = 0.f;    // h1(0) = 0
        __syncthreads();

        // xpre prefetch mapping: thread -> (b=warp, gate, j-pair)
        const int xg = lane >> 4;
        const int xj = (lane & 15) * 2;
        const float* xsrc = g_xpre + (size_t)(g * BG + warp) * T_ * 512 + xg * 256 + j0 + xj;
        float* xd = xs + (xg * 8 + warp) * 32 + xj;
        float2 xv = __ldcg((const float2*)xsrc);
        unsigned* cnt = g_cnt1[g];

        CL_ARRIVE();
        for (int t = 0; t < T_; ++t) {
            CL_WAIT();                                      // h1(t) fully delivered
            xd[0] = xv.x; xd[1] = xv.y;
            if (t + 1 < T_) xv = __ldcg((const float2*)(xsrc + (size_t)(t + 1) * 512));

            const float* hb = bufA + (t & 1) * 2048 + warp * 32;
            u64 af[8], ac[8];
#pragma unroll
            for (int b = 0; b < 8; ++b) { af[b] = 0; ac[b] = 0; }
#pragma unroll
            for (int q = 0; q < 8; ++q) {
#pragma unroll
                for (int b = 0; b < 8; ++b) {
                    ulonglong2 h2 = *(const ulonglong2*)(hb + b * 256 + q * 4);
                    af[b] = fma2(h2.x, wf[2 * q], af[b]);
                    af[b] = fma2(h2.y, wf[2 * q + 1], af[b]);
                    ac[b] = fma2(h2.x, wc[2 * q], ac[b]);
                    ac[b] = fma2(h2.y, wc[2 * q + 1], ac[b]);
                }
            }
#pragma unroll
            for (int b = 0; b < 8; ++b) {
                red[((0 * 8 + warp) * 8 + b) * 32 + lane] = af[b];
                red[((1 * 8 + warp) * 8 + b) * 32 + lane] = ac[b];
            }
            __syncthreads();
            {   // reduce/gate: thread = (j=lane, b=warp)
                const int b = warp;
                u64 sf = red[((0 * 8 + 0) * 8 + b) * 32 + lane];
                u64 sc = red[((1 * 8 + 0) * 8 + b) * 32 + lane];
#pragma unroll
                for (int q = 1; q < 8; ++q) {
                    sf = add2(sf, red[((0 * 8 + q) * 8 + b) * 32 + lane]);
                    sc = add2(sc, red[((1 * 8 + q) * 8 + b) * 32 + lane]);
                }
                float e, o;
                unpack2(sf, e, o); float pf = e + o + xs[(0 * 8 + b) * 32 + lane];
                unpack2(sc, e, o); float pc = e + o + xs[(8 + b) * 32 + lane];
                float f = sigm(pf);
                float cg = tanh_f(pc);
                float hold = bufA[(t & 1) * 2048 + b * 256 + jg];
                float hn = fmaf(f, hold - cg, cg);
                uint32_t off = (uint32_t)(((t + 1) & 1) * 8192 + b * 1024 + jg * 4);
#pragma unroll
                for (int r = 0; r < 8; ++r) st_cluster_f32(rem[r] + off, hn);
                g_y1t[((size_t)(t + 1) * GRP + g) * 2048 + b * 256 + jg] = hn;
                if (t == T_ - 1) out[OUT_Y2 + (size_t)(g * BG + b) * H_ + jg] = hn;
            }
            CL_ARRIVE();                                   // release pushes
            __syncthreads();
            if (tid == 0) red_add1(&cnt[t]);               // publish y slab t+1
        }
        CL_WAIT();
    } else {
        // ================= Layer 2: one cluster per group =================
        u64 wf[32], wc[32];
#pragma unroll
        for (int p = 0; p < 32; ++p) {
            int k = warp * 64 + 2 * p;
            wf[p] = pack2(Wf2[(size_t)k * H_ + jg], Wf2[(size_t)(k + 1) * H_ + jg]);
            wc[p] = pack2(Wc2[(size_t)k * H_ + jg], Wc2[(size_t)(k + 1) * H_ + jg]);
        }
        const float bfv = __ldg(bf2 + jg);
        const float bcv = __ldg(bc2 + jg);
        uint32_t rem[8];
#pragma unroll
        for (int r = 0; r < 8; ++r) rem[r] = mapa_u32(s2u(bufB), r);

        for (int i = tid; i < 2048; i += TPB) bufB[i] = 0.f;    // h2(0) = 0
        if (tid == 0) { mbar_init(mb0, 1); mbar_init(mb1, 1); }
        __syncthreads();

        unsigned* cnt = g_cnt1[g];
        if (tid == 0) {     // prefetch y(0) -> bufA[0]
            while (ld_acq(&cnt[0]) < CLU) __nanosleep(40);
            fence_async();
            mbar_expect(mb0, 8192);
            bulk_g2s(s2u(bufA), g_y1t + ((size_t)1 * GRP + g) * 2048, 8192, mb0);
        }
        CL_ARRIVE();
        unsigned phy[2] = {0, 0};
        for (int u = 0; u < T_; ++u) {
            CL_WAIT();                                     // h2(u) delivered
            if (tid == 0 && u + 1 < T_) {                  // prefetch y(u+1)
                while (ld_acq(&cnt[u + 1]) < CLU) __nanosleep(30);
                fence_async();
                uint32_t mb = ((u + 1) & 1) ? mb1 : mb0;
                mbar_expect(mb, 8192);
                bulk_g2s(s2u(bufA) + ((u + 1) & 1) * 8192,
                         g_y1t + ((size_t)(u + 2) * GRP + g) * 2048, 8192, mb);
            }
            const float* hb;
            if (warp < 4) {
                int bi = u & 1;
                mbar_wait(bi ? mb1 : mb0, phy[bi]);
                phy[bi] ^= 1;
                hb = bufA + bi * 2048 + warp * 64;
            } else {
                hb = bufB + (u & 1) * 2048 + (warp - 4) * 64;
            }
            u64 af[8], ac[8];
#pragma unroll
            for (int b = 0; b < 8; ++b) { af[b] = 0; ac[b] = 0; }
#pragma unroll
            for (int q = 0; q < 16; ++q) {
#pragma unroll
                for (int b = 0; b < 8; ++b) {
                    ulonglong2 h2 = *(const ulonglong2*)(hb + b * 256 + q * 4);
                    af[b] = fma2(h2.x, wf[2 * q], af[b]);
                    af[b] = fma2(h2.y, wf[2 * q + 1], af[b]);
                    ac[b] = fma2(h2.x, wc[2 * q], ac[b]);
                    ac[b] = fma2(h2.y, wc[2 * q + 1], ac[b]);
                }
            }
#pragma unroll
            for (int b = 0; b < 8; ++b) {
                red[((0 * 8 + warp) * 8 + b) * 32 + lane] = af[b];
                red[((1 * 8 + warp) * 8 + b) * 32 + lane] = ac[b];
            }
            __syncthreads();
            {   // reduce/gate: thread = (j=lane, b=warp)
                const int b = warp;
                u64 sf = red[((0 * 8 + 0) * 8 + b) * 32 + lane];
                u64 sc = red[((1 * 8 + 0) * 8 + b) * 32 + lane];
#pragma unroll
                for (int q = 1; q < 8; ++q) {
                    sf = add2(sf, red[((0 * 8 + q) * 8 + b) * 32 + lane]);
                    sc = add2(sc, red[((1 * 8 + q) * 8 + b) * 32 + lane]);
                }
                float e, o;
                unpack2(sf, e, o); float pf = e + o + bfv;
                unpack2(sc, e, o); float pc = e + o + bcv;
                float f = sigm(pf);
                float cg = tanh_f(pc);
                float hold = bufB[(u & 1) * 2048 + b * 256 + jg];
                float hn = fmaf(f, hold - cg, cg);
                uint32_t off = (uint32_t)(((u + 1) & 1) * 8192 + b * 1024 + jg * 4);
#pragma unroll
                for (int r = 0; r < 8; ++r) st_cluster_f32(rem[r] + off, hn);
                out[((size_t)(g * BG + b) * T_ + u) * H_ + jg] = hn;
                if (u == T_ - 1)
                    out[OUT_Y2 + (size_t)B_ * H_ + (size_t)(g * BG + b) * H_ + jg] = hn;
            }
            CL_ARRIVE();
        }
        CL_WAIT();
    }
}

// ============================================================
extern "C" void kernel_launch(void* const* d_in, const int* in_sizes, int n_in,
                              void* d_out, int out_size)
{
    const float* x   = (const float*)d_in[0];
    const float* Wf1 = (const float*)d_in[1];
    const float* bf1 = (const float*)d_in[2];
    const float* Wc1 = (const float*)d_in[3];
    const float* bc1 = (const float*)d_in[4];
    const float* Wf2 = (const float*)d_in[5];
    const float* bf2 = (const float*)d_in[6];
    const float* Wc2 = (const float*)d_in[7];
    const float* bc2 = (const float*)d_in[8];
    float* out = (float*)d_out;

    cudaFuncSetAttribute((const void*)recur_kernel,
                         cudaFuncAttributeMaxDynamicSharedMemorySize, SMEM_BYTES);

    init_kernel<<<64, 256>>>();
    xproj_kernel<<<dim3(1024, 8), 256>>>(x, Wf1, bf1, Wc1, bc1);
    recur_kernel<<<NCTA, TPB, SMEM_BYTES>>>(Wf1, Wc1, Wf2, bf2, Wc2, bc2, out);
}

// round 7
// speedup vs baseline: 1.6259x; 1.6259x over previous
#include <cuda_runtime.h>
#include <cstdint>
#include <cstddef>

// Problem constants
#define B_ 64
#define T_ 1024
#define I_ 128
#define H_ 256

#define GRP 8              // batch groups
#define BG 8               // batches per group
#define CPG 8              // CTAs per (layer, group)
#define NCTA 128           // 64 L1 + 64 L2
#define TPB 256

#define OUT_Y2 ((size_t)B_ * T_ * H_)

// -------- device scratch --------
__device__ __align__(16) float g_xpre[(size_t)B_ * T_ * 512];            // [b][t][512]
__device__ __align__(16) float g_y1t[(size_t)(T_ + 1) * GRP * 2048];     // [t][g][b][k] 8KB slabs
__device__ __align__(16) float g_h2t[2][GRP][2048];                      // [par][g][b][k]
__device__ unsigned g_cnt1[GRP][T_ + 1];
__device__ unsigned g_cnt2[GRP][T_ + 1];

// -------- PTX helpers --------
typedef unsigned long long u64;
__device__ __forceinline__ uint32_t s2u(const void* p) {
    return (uint32_t)__cvta_generic_to_shared(p);
}
__device__ __forceinline__ void mbar_init(uint32_t a, uint32_t cnt) {
    asm volatile("mbarrier.init.shared.b64 [%0], %1;" :: "r"(a), "r"(cnt) : "memory");
}
__device__ __forceinline__ void mbar_expect(uint32_t a, uint32_t bytes) {
    asm volatile("mbarrier.arrive.expect_tx.shared.b64 _, [%0], %1;" :: "r"(a), "r"(bytes) : "memory");
}
__device__ __forceinline__ void bulk_g2s(uint32_t dst, const void* src, uint32_t bytes, uint32_t mbar) {
    asm volatile("cp.async.bulk.shared::cluster.global.mbarrier::complete_tx::bytes [%0], [%1], %2, [%3];"
                 :: "r"(dst), "l"(src), "r"(bytes), "r"(mbar) : "memory");
}
__device__ __forceinline__ void mbar_wait(uint32_t a, uint32_t parity) {
    asm volatile("{\n\t"
                 ".reg .pred P;\n\t"
                 "W%=:\n\t"
                 "mbarrier.try_wait.parity.acquire.cta.shared::cta.b64 P, [%0], %1, 0x989680;\n\t"
                 "@P bra D%=;\n\t"
                 "bra W%=;\n\t"
                 "D%=:\n\t"
                 "}" :: "r"(a), "r"(parity) : "memory");
}
__device__ __forceinline__ void fence_async() {
    asm volatile("fence.proxy.async.shared::cta;" ::: "memory");
}
__device__ __forceinline__ unsigned ld_acq(const unsigned* p) {
    unsigned v;
    asm volatile("ld.global.acquire.gpu.u32 %0, [%1];" : "=r"(v) : "l"(p) : "memory");
    return v;
}
__device__ __forceinline__ void red_add1(unsigned* p) {
    asm volatile("red.release.gpu.global.add.u32 [%0], %1;" :: "l"(p), "r"(1u) : "memory");
}
__device__ __forceinline__ u64 pack2(float x, float y) {
    u64 r; asm("mov.b64 %0, {%1, %2};" : "=l"(r) : "f"(x), "f"(y)); return r;
}
__device__ __forceinline__ void unpack2(u64 v, float& x, float& y) {
    asm("mov.b64 {%0, %1}, %2;" : "=f"(x), "=f"(y) : "l"(v));
}
__device__ __forceinline__ u64 fma2(u64 a, u64 b, u64 c) {
    u64 d; asm("fma.rn.f32x2 %0, %1, %2, %3;" : "=l"(d) : "l"(a), "l"(b), "l"(c)); return d;
}
__device__ __forceinline__ u64 add2(u64 a, u64 b) {
    u64 d; asm("add.rn.f32x2 %0, %1, %2;" : "=l"(d) : "l"(a), "l"(b)); return d;
}
__device__ __forceinline__ float sigm(float x) { return 1.f / (1.f + __expf(-x)); }
__device__ __forceinline__ float tanh_f(float x) { return 1.f - 2.f / (1.f + __expf(2.f * x)); }

// ============================================================
// Phase 1: x-projection GEMM (unchanged)
// ============================================================
__global__ void __launch_bounds__(256) xproj_kernel(
    const float* __restrict__ x,
    const float* __restrict__ Wf1, const float* __restrict__ bf1,
    const float* __restrict__ Wc1, const float* __restrict__ bc1)
{
    __shared__ float As[64][68];
    __shared__ float Bs[64][68];
    const int bm = blockIdx.x;
    const int bn = blockIdx.y;
    const int tid = threadIdx.x;
    const int tx = tid & 15, ty = tid >> 4;

    const float* W; const float* bias; int jb;
    if (bn < 4) { W = Wf1; bias = bf1; jb = bn * 64; }
    else        { W = Wc1; bias = bc1; jb = (bn - 4) * 64; }

    float acc[4][4];
#pragma unroll
    for (int i = 0; i < 4; ++i)
#pragma unroll
        for (int j = 0; j < 4; ++j) acc[i][j] = 0.f;

    for (int k0 = 0; k0 < 128; k0 += 64) {
#pragma unroll
        for (int i = 0; i < 4; ++i) {
            int idx = tid + i * 256;
            int r = idx >> 4, kv = idx & 15;
            float4 v = *(const float4*)(x + (size_t)(bm * 64 + r) * 128 + k0 + kv * 4);
            *(float4*)&As[r][kv * 4] = v;
        }
#pragma unroll
        for (int i = 0; i < 4; ++i) {
            int idx = tid + i * 256;
            int kk = idx >> 4, cv = idx & 15;
            float4 v = *(const float4*)(W + (size_t)(k0 + kk) * 256 + jb + cv * 4);
            *(float4*)&Bs[kk][cv * 4] = v;
        }
        __syncthreads();
#pragma unroll 16
        for (int kk = 0; kk < 64; ++kk) {
            float a0 = As[ty * 4 + 0][kk];
            float a1 = As[ty * 4 + 1][kk];
            float a2 = As[ty * 4 + 2][kk];
            float a3 = As[ty * 4 + 3][kk];
            float4 bv = *(const float4*)&Bs[kk][tx * 4];
            acc[0][0] = fmaf(a0, bv.x, acc[0][0]);
            acc[0][1] = fmaf(a0, bv.y, acc[0][1]);
            acc[0][2] = fmaf(a0, bv.z, acc[0][2]);
            acc[0][3] = fmaf(a0, bv.w, acc[0][3]);
            acc[1][0] = fmaf(a1, bv.x, acc[1][0]);
            acc[1][1] = fmaf(a1, bv.y, acc[1][1]);
            acc[1][2] = fmaf(a1, bv.z, acc[1][2]);
            acc[1][3] = fmaf(a1, bv.w, acc[1][3]);
            acc[2][0] = fmaf(a2, bv.x, acc[2][0]);
            acc[2][1] = fmaf(a2, bv.y, acc[2][1]);
            acc[2][2] = fmaf(a2, bv.z, acc[2][2]);
            acc[2][3] = fmaf(a2, bv.w, acc[2][3]);
            acc[3][0] = fmaf(a3, bv.x, acc[3][0]);
            acc[3][1] = fmaf(a3, bv.y, acc[3][1]);
            acc[3][2] = fmaf(a3, bv.z, acc[3][2]);
            acc[3][3] = fmaf(a3, bv.w, acc[3][3]);
        }
        __syncthreads();
    }
#pragma unroll
    for (int i = 0; i < 4; ++i) {
        int r = bm * 64 + ty * 4 + i;
        float4 o;
        o.x = acc[i][0] + bias[jb + tx * 4 + 0];
        o.y = acc[i][1] + bias[jb + tx * 4 + 1];
        o.z = acc[i][2] + bias[jb + tx * 4 + 2];
        o.w = acc[i][3] + bias[jb + tx * 4 + 3];
        *(float4*)&g_xpre[(size_t)r * 512 + bn * 64 + tx * 4] = o;
    }
}

// ============================================================
__global__ void init_kernel()
{
    int i = blockIdx.x * blockDim.x + threadIdx.x;      // 32768 threads
    if (i < GRP * 2048) g_y1t[i] = 0.f;                 // y1 slab t=0
    if (i < GRP * (T_ + 1)) {
        ((unsigned*)g_cnt1)[i] = 0;
        ((unsigned*)g_cnt2)[i] = 0;
    }
}

// ============================================================
// Phase 2: persistent recurrence — R6 compute layout, R5 sync
//   SMEM (dynamic):
//     [    0, 16384): bufY[2][2048]  -- L1: h1 buf (first 8KB) | L2: y dbl-buf
//     [16384, 24576): bufH[2048]     -- L2 h2 buf
//     [24576, 57344): red u64[2][8][8][32]  [gate][kwarp][b][lane]
//     [57344, 59392): xs[2][8][32]   -- L1 xpre staging [gate][b][j]
//     [59392, 59424): mbars
// ============================================================
#define SM_Y    0
#define SM_H    16384
#define SM_RED  24576
#define SM_XS   57344
#define SM_MBAR 59392
#define SMEM_BYTES 59424

extern __shared__ __align__(16) char smem[];

__global__ void __launch_bounds__(TPB, 1)
recur_kernel(const float* __restrict__ Wf1, const float* __restrict__ Wc1,
             const float* __restrict__ Wf2, const float* __restrict__ bf2,
             const float* __restrict__ Wc2, const float* __restrict__ bc2,
             float* __restrict__ out)
{
    const int tid = threadIdx.x;
    const int warp = tid >> 5, lane = tid & 31;
    const int cid = blockIdx.x;
    const bool isL1 = cid < 64;
    const int g = (cid & 63) >> 3;
    const int rank = cid & 7;
    const int j0 = rank * 32;
    const int jg = j0 + lane;

    float* bufY = (float*)(smem + SM_Y);
    float* bufH = (float*)(smem + SM_H);
    u64*   red  = (u64*)(smem + SM_RED);
    float* xs   = (float*)(smem + SM_XS);
    const uint32_t mb0 = s2u(smem + SM_MBAR);       // L1: h1 | L2: y buf0
    const uint32_t mb1 = mb0 + 8;                   // L2: y buf1
    const uint32_t mbH = mb0 + 16;                  // L2: h2

    if (isL1) {
        // ================= Layer 1 =================
        u64 wf[16], wc[16];
#pragma unroll
        for (int p = 0; p < 16; ++p) {
            int k = warp * 32 + 2 * p;
            wf[p] = pack2(Wf1[(size_t)(I_ + k) * H_ + jg], Wf1[(size_t)(I_ + k + 1) * H_ + jg]);
            wc[p] = pack2(Wc1[(size_t)(I_ + k) * H_ + jg], Wc1[(size_t)(I_ + k + 1) * H_ + jg]);
        }
        if (tid == 0) mbar_init(mb0, 1);
        __syncthreads();

        // xpre prefetch: thread -> (b=warp, gate=lane>>4, j-pair)
        const int xg = lane >> 4;
        const int xj = (lane & 15) * 2;
        const float* xsrc = g_xpre + (size_t)(g * BG + warp) * T_ * 512 + xg * 256 + j0 + xj;
        float* xd = xs + (xg * 8 + warp) * 32 + xj;
        float2 xv = __ldcg((const float2*)xsrc);
        unsigned* cnt = g_cnt1[g];

        unsigned ph = 0;
        for (int t = 0; t < T_; ++t) {
            if (tid == 0) {
                if (t > 0) { while (ld_acq(&cnt[t - 1]) < CPG) __nanosleep(20); }
                fence_async();
                mbar_expect(mb0, 8192);
                bulk_g2s(s2u(bufY), g_y1t + ((size_t)t * GRP + g) * 2048, 8192, mb0);
            }
            xd[0] = xv.x; xd[1] = xv.y;
            if (t + 1 < T_) xv = __ldcg((const float2*)(xsrc + (size_t)(t + 1) * 512));

            mbar_wait(mb0, ph);
            u64 af[8], ac[8];
#pragma unroll
            for (int b = 0; b < 8; ++b) { af[b] = 0; ac[b] = 0; }
#pragma unroll
            for (int b = 0; b < 8; ++b) {
                const float* base = bufY + b * 256 + warp * 32;
#pragma unroll
                for (int q = 0; q < 8; ++q) {
                    ulonglong2 h2 = *(const ulonglong2*)(base + q * 4);
                    af[b] = fma2(h2.x, wf[2 * q], af[b]);
                    af[b] = fma2(h2.y, wf[2 * q + 1], af[b]);
                    ac[b] = fma2(h2.x, wc[2 * q], ac[b]);
                    ac[b] = fma2(h2.y, wc[2 * q + 1], ac[b]);
                }
            }
#pragma unroll
            for (int b = 0; b < 8; ++b) {
                red[((0 * 8 + warp) * 8 + b) * 32 + lane] = af[b];
                red[((1 * 8 + warp) * 8 + b) * 32 + lane] = ac[b];
            }
            __syncthreads();
            {   // gate: thread = (b=warp, col=lane)
                const int b = warp;
                u64 sf = red[((0 * 8 + 0) * 8 + b) * 32 + lane];
                u64 sc = red[((1 * 8 + 0) * 8 + b) * 32 + lane];
#pragma unroll
                for (int q = 1; q < 8; ++q) {
                    sf = add2(sf, red[((0 * 8 + q) * 8 + b) * 32 + lane]);
                    sc = add2(sc, red[((1 * 8 + q) * 8 + b) * 32 + lane]);
                }
                float e, o;
                unpack2(sf, e, o); float pf = e + o + xs[(0 * 8 + b) * 32 + lane];
                unpack2(sc, e, o); float pc = e + o + xs[(8 + b) * 32 + lane];
                float f = sigm(pf);
                float cg = tanh_f(pc);
                float hold = bufY[b * 256 + jg];
                float hn = fmaf(f, hold - cg, cg);
                g_y1t[((size_t)(t + 1) * GRP + g) * 2048 + b * 256 + jg] = hn;
                if (t == T_ - 1) out[OUT_Y2 + (size_t)(g * BG + b) * H_ + jg] = hn;
            }
            __syncthreads();
            if (tid == 0) red_add1(&cnt[t]);
            ph ^= 1;
        }
    } else {
        // ================= Layer 2 =================
        u64 wf[32], wc[32];
#pragma unroll
        for (int p = 0; p < 32; ++p) {
            int k = warp * 64 + 2 * p;
            wf[p] = pack2(Wf2[(size_t)k * H_ + jg], Wf2[(size_t)(k + 1) * H_ + jg]);
            wc[p] = pack2(Wc2[(size_t)k * H_ + jg], Wc2[(size_t)(k + 1) * H_ + jg]);
        }
        const float bfv = __ldg(bf2 + jg);
        const float bcv = __ldg(bc2 + jg);

        for (int i = tid; i < 2048; i += TPB) bufH[i] = 0.f;    // h2(0) = 0
        if (tid == 0) { mbar_init(mb0, 1); mbar_init(mb1, 1); mbar_init(mbH, 1); }
        __syncthreads();

        unsigned* cnt1p = g_cnt1[g];
        unsigned* cnt2p = g_cnt2[g];
        if (tid == 160) {       // prefetch y(0) -> bufY[0]
            while (ld_acq(&cnt1p[0]) < CPG) __nanosleep(30);
            fence_async();
            mbar_expect(mb0, 8192);
            bulk_g2s(s2u(bufY), g_y1t + ((size_t)1 * GRP + g) * 2048, 8192, mb0);
        }

        unsigned phy[2] = {0, 0}, phH = 0;
        for (int u = 0; u < T_; ++u) {
            if (tid == 128 && u > 0) {       // h2 pull (critical)
                while (ld_acq(&cnt2p[u - 1]) < CPG) __nanosleep(20);
                fence_async();
                mbar_expect(mbH, 8192);
                bulk_g2s(s2u(bufH), g_h2t[u & 1][g], 8192, mbH);
            }
            if (tid == 160 && u + 1 < T_) {  // y prefetch for u+1
                while (ld_acq(&cnt1p[u + 1]) < CPG) __nanosleep(20);
                fence_async();
                uint32_t mb = ((u + 1) & 1) ? mb1 : mb0;
                mbar_expect(mb, 8192);
                bulk_g2s(s2u(bufY) + ((u + 1) & 1) * 8192,
                         g_y1t + ((size_t)(u + 2) * GRP + g) * 2048, 8192, mb);
            }

            const float* hb; int kc;
            if (warp < 4) {
                int bi = u & 1;
                mbar_wait(bi ? mb1 : mb0, phy[bi]);
                phy[bi] ^= 1;
                hb = bufY + bi * 2048;
                kc = warp * 64;
            } else {
                if (u > 0) { mbar_wait(mbH, phH); phH ^= 1; }
                hb = bufH;
                kc = (warp - 4) * 64;
            }
            u64 af[8], ac[8];
#pragma unroll
            for (int b = 0; b < 8; ++b) { af[b] = 0; ac[b] = 0; }
#pragma unroll
            for (int b = 0; b < 8; ++b) {
                const float* base = hb + b * 256 + kc;
#pragma unroll
                for (int q = 0; q < 16; ++q) {
                    ulonglong2 h2 = *(const ulonglong2*)(base + q * 4);
                    af[b] = fma2(h2.x, wf[2 * q], af[b]);
                    af[b] = fma2(h2.y, wf[2 * q + 1], af[b]);
                    ac[b] = fma2(h2.x, wc[2 * q], ac[b]);
                    ac[b] = fma2(h2.y, wc[2 * q + 1], ac[b]);
                }
            }
#pragma unroll
            for (int b = 0; b < 8; ++b) {
                red[((0 * 8 + warp) * 8 + b) * 32 + lane] = af[b];
                red[((1 * 8 + warp) * 8 + b) * 32 + lane] = ac[b];
            }
            __syncthreads();
            {   // gate: thread = (b=warp, col=lane)
                const int b = warp;
                u64 sf = red[((0 * 8 + 0) * 8 + b) * 32 + lane];
                u64 sc = red[((1 * 8 + 0) * 8 + b) * 32 + lane];
#pragma unroll
                for (int q = 1; q < 8; ++q) {
                    sf = add2(sf, red[((0 * 8 + q) * 8 + b) * 32 + lane]);
                    sc = add2(sc, red[((1 * 8 + q) * 8 + b) * 32 + lane]);
                }
                float e, o;
                unpack2(sf, e, o); float pf = e + o + bfv;
                unpack2(sc, e, o); float pc = e + o + bcv;
                float f = sigm(pf);
                float cg = tanh_f(pc);
                float hold = bufH[b * 256 + jg];
                float hn = fmaf(f, hold - cg, cg);
                g_h2t[(u + 1) & 1][g][b * 256 + jg] = hn;
                out[((size_t)(g * BG + b) * T_ + u) * H_ + jg] = hn;
                if (u == T_ - 1)
                    out[OUT_Y2 + (size_t)B_ * H_ + (size_t)(g * BG + b) * H_ + jg] = hn;
            }
            __syncthreads();
            if (tid == 0) red_add1(&cnt2p[u]);
        }
    }
}

// ============================================================
extern "C" void kernel_launch(void* const* d_in, const int* in_sizes, int n_in,
                              void* d_out, int out_size)
{
    const float* x   = (const float*)d_in[0];
    const float* Wf1 = (const float*)d_in[1];
    const float* bf1 = (const float*)d_in[2];
    const float* Wc1 = (const float*)d_in[3];
    const float* bc1 = (const float*)d_in[4];
    const float* Wf2 = (const float*)d_in[5];
    const float* bf2 = (const float*)d_in[6];
    const float* Wc2 = (const float*)d_in[7];
    const float* bc2 = (const float*)d_in[8];
    float* out = (float*)d_out;

    cudaFuncSetAttribute((const void*)recur_kernel,
                         cudaFuncAttributeMaxDynamicSharedMemorySize, SMEM_BYTES);

    init_kernel<<<128, 256>>>();
    xproj_kernel<<<dim3(1024, 8), 256>>>(x, Wf1, bf1, Wc1, bc1);
    recur_kernel<<<NCTA, TPB, SMEM_BYTES>>>(Wf1, Wc1, Wf2, bf2, Wc2, bc2, out);
}